// round 15
// baseline (speedup 1.0000x reference)
#include <cuda_runtime.h>

// YOLOLoss fused, round 15: identical resubmission of round 14 (bench failed on
// a pre-launch "system not yet initialized" infra error, not a kernel fault).
// Barrier-free warp-autonomous design: 352 blocks x 512 threads, ZERO
// __syncthreads. Cross-warp coupling only via named barriers among the 2 target
// warps of each half (s_meta exchange). All accumulation via fanned-out global
// REDGs; warp-granular completion.

#define BSZ     32
#define NT      50
#define HH      104
#define WW      104
#define HW      (HH*WW)                 // 10816
#define NCLS    20
#define BLK_POS 512                     // 256 thr-per-batch x 2 positions
#define NBX     22
#define NBLK    (NBX * (BSZ/2))         // 352
#define NWARP   (NBLK * 16)             // 5632 warps total
#define WQUOTA  (NWARP / 32)            // 176 warps per counter slot
#define NCELL   ((double)(BSZ * 3 * HW))

__device__ double   g_acc[8];           // sparse terms (zero-init; reset by finalizer)
__device__ double   g_dense[32];        // dense softplus partials, fanned out
__device__ unsigned g_wctr[32];         // warp-completion slots
__device__ unsigned g_fctr;             // slot-completion counter

// min(softplus(z), 100) == -clip(log(1-sigmoid(z)), -100); spl(-z) == -clip(log(sigmoid(z)), -100)
__device__ __forceinline__ float spl(float z) {
    return fminf(__logf(1.0f + __expf(z)), 100.0f);
}

__global__ __launch_bounds__(512)
void yolo_fused(const float* __restrict__ in, const float* __restrict__ tg,
                float* __restrict__ out)
{
    __shared__ int s_meta[2][NT];       // per half-block batch

    const int tid  = threadIdx.x;
    const int half = tid >> 8;          // 0 or 1 -> which batch
    const int htid = tid & 255;         // thread id within half
    const int b    = blockIdx.y * 2 + half;
    const int P0   = blockIdx.x * BLK_POS;
    const int lane = tid & 31, wrp = tid >> 5;
    const int gw   = (blockIdx.y * NBX + blockIdx.x) * 16 + wrp;  // global warp id
    const int slot = gw & 31;
    const bool twarp = (htid < 64);     // warps 0,1 (half0) / 8,9 (half1): target warps

    // ---- dense conf loads: 2 positions x 3 anchors, issued first ----
    const int  p0   = P0 + htid * 2;
    const bool live = (p0 < HW);        // HW even -> full pairs
    const float* base = in + (size_t)b * 75 * HW;
    float2 c0, c1, c2;
    if (live) {
        c0 = *(const float2*)(base + (size_t)( 4) * HW + p0);
        c1 = *(const float2*)(base + (size_t)(29) * HW + p0);
        c2 = *(const float2*)(base + (size_t)(54) * HW + p0);
    }

    // ---- per-target prologue (htid 0..49 of each half) ----
    int  mymeta = 0;
    bool inr = false;
    float mytx = 0.f, myty = 0.f, mytw = 0.f, myth = 0.f;
    if (htid < NT) {
        const float* t = tg + ((size_t)b * NT + htid) * 5;
        float t0 = t[0], t1 = t[1], t2 = t[2], t3 = t[3], t4 = t[4];
        int meta = 0x7FFFFFFF;          // invalid: low14 = 16383 > any pos
        if (t0 + t1 + t2 + t3 + t4 > 0.0f) {
            float gx = t0 * (float)WW, gy = t1 * (float)HH;
            float gw2 = t2 * (float)WW, gh = t3 * (float)HH;
            int gi = (int)gx, gj = (int)gy;
            const float aw[3] = {14.5f, 19.5f, 46.625f};   // ANCHORS / 8
            const float ah[3] = {11.25f, 24.75f, 40.75f};
            float area = (gw2 + 1.0f) * (gh + 1.0f);
            float best = -1.0f; int bn = 0, nz = 0;
            #pragma unroll
            for (int a = 0; a < 3; a++) {
                float inter = fmaxf(fminf(gw2, aw[a]) + 1.0f, 0.0f) *
                              fmaxf(fminf(gh, ah[a]) + 1.0f, 0.0f);
                float iou = inter / (area + (aw[a] + 1.0f) * (ah[a] + 1.0f) - inter + 1e-16f);
                if (iou > best) { best = iou; bn = a; }      // first max wins
                if (iou > 0.5f) nz |= (1 << a);
            }
            mytx = gx - (float)gi;
            myty = gy - (float)gj;
            mytw = __logf(gw2 / aw[bn] + 1e-16f);
            myth = __logf(gh / ah[bn] + 1e-16f);
            int pos = gj * WW + gi;
            meta = pos | (bn << 14) | (nz << 16) | (((int)t4) << 19);
            inr = (pos >= P0) && (pos < P0 + BLK_POS);
        }
        s_meta[half][htid] = meta;
        mymeta = meta;
    }

    // ---- speculative loads for in-range targets (pre-named-barrier) ----
    float vx = 0, vy = 0, vw = 0, vh = 0, vc = 0, cfa0 = 0, cfa1 = 0, cfa2 = 0;
    int   mypos = 0, mya = 0;
    if (inr) {
        mypos = mymeta & 0x3FFF;
        mya   = (mymeta >> 14) & 3;
        const float* ch = base + (size_t)(mya * 25) * HW + mypos;
        vx = ch[0]; vy = ch[HW]; vw = ch[2 * HW]; vh = ch[3 * HW]; vc = ch[4 * HW];
        cfa0 = base[(size_t)( 4) * HW + mypos];
        cfa1 = base[(size_t)(29) * HW + mypos];
        cfa2 = base[(size_t)(54) * HW + mypos];
    }

    // ---- dense math: log of products (6 EX2 + 1 LG2), warp SHFL reduce ----
    float a_no = 0.0f;
    if (live) {
        float e0 = __expf(c0.x), e1 = __expf(c0.y);
        float e2 = __expf(c1.x), e3 = __expf(c1.y);
        float e4 = __expf(c2.x), e5 = __expf(c2.y);
        float P = (1.0f + e0);
        P = fmaf(P, e1, P);             // P *= (1+e_k)
        P = fmaf(P, e2, P);
        P = fmaf(P, e3, P);
        P = fmaf(P, e4, P);
        P = fmaf(P, e5, P);
        a_no = __logf(P);               // == sum of 6 softplus values
    }
    #pragma unroll
    for (int off = 16; off > 0; off >>= 1)
        a_no += __shfl_down_sync(0xFFFFFFFFu, a_no, off);
    if (lane == 0 && a_no != 0.0f)
        atomicAdd(&g_dense[slot], (double)a_no);   // fanned REDG (176 ops/addr)

    // ---- target resolution: only the 4 target warps; named barrier per half ----
    if (twarp) {
        if (half == 0) asm volatile("bar.sync 1, 64;" ::: "memory");
        else           asm volatile("bar.sync 2, 64;" ::: "memory");

        if (inr) {
            int      mynz  = (mymeta >> 16) & 7;
            unsigned cm    = 1u << ((mymeta >> 19) & 31);
            bool     alive = true;
            int      subnz = mynz;
            for (int u = 0; u < NT; u++) {
                if (u == htid) continue;
                int mu = s_meta[half][u];
                if ((mu & 0x3FFF) != mypos) continue;
                if (((mu >> 14) & 3) == mya) {
                    if (u > htid) alive = false;                 // last duplicate wins
                    else          cm |= 1u << ((mu >> 19) & 31); // union earlier classes
                }
                if (u < htid) subnz &= ~((mu >> 16) & 7);        // earlier owner subtracts
            }
            float sub = 0.0f;           // remove ignored cells from dense sum
            if (subnz & 1) sub += spl(cfa0);
            if (subnz & 2) sub += spl(cfa1);
            if (subnz & 4) sub += spl(cfa2);
            if (sub != 0.0f) atomicAdd(&g_acc[5], (double)(-sub));

            if (alive) {
                const float* ch = base + (size_t)(mya * 25) * HW + mypos;
                float pc[NCLS];
                #pragma unroll
                for (int c = 0; c < NCLS; c++) pc[c] = ch[(size_t)(5 + c) * HW];
                float scl = 0.0f;
                #pragma unroll
                for (int c = 0; c < NCLS; c++)
                    scl += spl(((cm >> c) & 1) ? -pc[c] : pc[c]);
                // BCE(sigm(z), t) = t*spl(-z) + (1-t)*spl(z)
                atomicAdd(&g_acc[0], (double)(mytx * spl(-vx) + (1.0f - mytx) * spl(vx)));
                atomicAdd(&g_acc[1], (double)(myty * spl(-vy) + (1.0f - myty) * spl(vy)));
                float dw = vw - mytw, dh = vh - myth;
                atomicAdd(&g_acc[2], (double)(dw * dw));
                atomicAdd(&g_acc[3], (double)(dh * dh));
                atomicAdd(&g_acc[4], (double)spl(-vc));
                atomicAdd(&g_acc[6], (double)scl);
                atomicAdd(&g_acc[7], 1.0);
            }
        }
    }

    // ---- warp-granular completion (no block barriers anywhere) ----
    __threadfence();                    // each lane orders its own REDGs
    __syncwarp();                       // all lanes fenced before lane0 counts
    int last = 0;
    if (lane == 0) {
        if (atomicAdd(&g_wctr[slot], 1u) == WQUOTA - 1) {    // slot complete
            __threadfence();
            if (atomicAdd(&g_fctr, 1u) == 31) last = 1;      // all slots complete
        }
    }
    last = __shfl_sync(0xFFFFFFFFu, last, 0);

    // ---- finalizer warp ----
    if (last) {
        __threadfence();
        double D = atomicAdd(&g_dense[lane], 0.0);           // 32 parallel coherent reads
        double A = (lane < 8) ? atomicAdd(&g_acc[lane], 0.0) : 0.0;
        g_dense[lane] = 0.0;                                 // reset for next replay
        g_wctr[lane]  = 0u;
        if (lane < 8) g_acc[lane] = 0.0;
        #pragma unroll
        for (int off = 16; off > 0; off >>= 1)
            D += __shfl_down_sync(0xFFFFFFFFu, D, off);      // total dense on lane 0
        double A0 = __shfl_sync(0xFFFFFFFFu, A, 0);
        double A1 = __shfl_sync(0xFFFFFFFFu, A, 1);
        double A2 = __shfl_sync(0xFFFFFFFFu, A, 2);
        double A3 = __shfl_sync(0xFFFFFFFFu, A, 3);
        double A4 = __shfl_sync(0xFFFFFFFFu, A, 4);
        double A5 = __shfl_sync(0xFFFFFFFFu, A, 5);
        double A6 = __shfl_sync(0xFFFFFFFFu, A, 6);
        double A7 = __shfl_sync(0xFFFFFFFFu, A, 7);
        if (lane == 0) {
            double sno = A5 + D;                             // dense sum + ignore corrections
            out[0] = (float)(2.5 * A0 / NCELL);
            out[1] = (float)(2.5 * A1 / NCELL);
            out[2] = (float)(2.5 * A2 / NCELL);
            out[3] = (float)(2.5 * A3 / NCELL);
            out[4] = (float)((A4 + 0.5 * sno) / NCELL);
            out[5] = (float)(A6 / fmax(A7 * 20.0, 1.0));
            __threadfence();
            g_fctr = 0u;
        }
    }
}

extern "C" void kernel_launch(void* const* d_in, const int* in_sizes, int n_in,
                              void* d_out, int out_size) {
    const float* in = (const float*)d_in[0];   // (32,75,104,104)
    const float* tg = (const float*)d_in[1];   // (32,50,5)
    float* out = (float*)d_out;                // 6 floats

    dim3 grid(NBX, BSZ / 2);                   // (22, 16) = 352 blocks x 512 thr
    yolo_fused<<<grid, 512>>>(in, tg, out);
}

// round 16
// speedup vs baseline: 1.6466x; 1.6466x over previous
#include <cuda_runtime.h>

// YOLOLoss fused, round 16: R13 lean structure, 12 elems/thread via 3x float4.
// 176 blocks x 512 threads (~1 wave), 2 batches/block, BLK_POS=1024.
// Dense: 3 float4 conf loads -> two 6-wide log-of-products (12 EX2 + 2 LG2).
// Tail: warp-0-only (R13). Two block barriers total.

#define BSZ     32
#define NT      50
#define HH      104
#define WW      104
#define HW      (HH*WW)                 // 10816
#define NCLS    20
#define BLK_POS 1024                    // 256 thr-per-batch x 4 positions
#define NBX     11                      // ceil(10816/1024)
#define NBLK    (NBX * (BSZ/2))         // 176
#define NCELL   ((double)(BSZ * 3 * HW))

__device__ double   g_acc[8];           // zero-init; reset by finalizer
__device__ unsigned g_ctr;

// min(softplus(z), 100) == -clip(log(1-sigmoid(z)), -100); spl(-z) == -clip(log(sigmoid(z)), -100)
__device__ __forceinline__ float spl(float z) {
    return fminf(__logf(1.0f + __expf(z)), 100.0f);
}

__global__ __launch_bounds__(512)
void yolo_fused(const float* __restrict__ in, const float* __restrict__ tg,
                float* __restrict__ out)
{
    __shared__ int   s_meta[2][NT];     // per half-block batch
    __shared__ float s_acc[8];          // sparse terms (atomic, few writers)
    __shared__ float s_no[16];          // per-warp dense partials (plain stores)

    const int tid  = threadIdx.x;
    const int half = tid >> 8;          // 0 or 1 -> which batch
    const int htid = tid & 255;         // thread id within half
    const int b    = blockIdx.y * 2 + half;
    const int P0   = blockIdx.x * BLK_POS;
    const int lane = tid & 31, wrp = tid >> 5;

    // ---- dense conf loads: 4 positions x 3 anchors = 3 x float4, issued first ----
    const int  p0   = P0 + htid * 4;
    const bool live = (p0 < HW);        // HW%4==0 -> full quads
    const float* base = in + (size_t)b * 75 * HW;
    float4 c0, c1, c2;
    if (live) {
        c0 = *(const float4*)(base + (size_t)( 4) * HW + p0);
        c1 = *(const float4*)(base + (size_t)(29) * HW + p0);
        c2 = *(const float4*)(base + (size_t)(54) * HW + p0);
    }
    if (tid < 8) s_acc[tid] = 0.0f;

    // ---- per-target prologue (htid 0..49 of each half) ----
    int  mymeta = 0;
    bool inr = false;
    float mytx = 0.f, myty = 0.f, mytw = 0.f, myth = 0.f;
    if (htid < NT) {
        const float* t = tg + ((size_t)b * NT + htid) * 5;
        float t0 = t[0], t1 = t[1], t2 = t[2], t3 = t[3], t4 = t[4];
        int meta = 0x7FFFFFFF;          // invalid: low14 = 16383 > any pos
        if (t0 + t1 + t2 + t3 + t4 > 0.0f) {
            float gx = t0 * (float)WW, gy = t1 * (float)HH;
            float gw = t2 * (float)WW, gh = t3 * (float)HH;
            int gi = (int)gx, gj = (int)gy;
            const float aw[3] = {14.5f, 19.5f, 46.625f};   // ANCHORS / 8
            const float ah[3] = {11.25f, 24.75f, 40.75f};
            float area = (gw + 1.0f) * (gh + 1.0f);
            float best = -1.0f; int bn = 0, nz = 0;
            #pragma unroll
            for (int a = 0; a < 3; a++) {
                float inter = fmaxf(fminf(gw, aw[a]) + 1.0f, 0.0f) *
                              fmaxf(fminf(gh, ah[a]) + 1.0f, 0.0f);
                float iou = inter / (area + (aw[a] + 1.0f) * (ah[a] + 1.0f) - inter + 1e-16f);
                if (iou > best) { best = iou; bn = a; }      // first max wins
                if (iou > 0.5f) nz |= (1 << a);
            }
            mytx = gx - (float)gi;
            myty = gy - (float)gj;
            mytw = __logf(gw / aw[bn] + 1e-16f);
            myth = __logf(gh / ah[bn] + 1e-16f);
            int pos = gj * WW + gi;
            meta = pos | (bn << 14) | (nz << 16) | (((int)t4) << 19);
            inr = (pos >= P0) && (pos < P0 + BLK_POS);
        }
        s_meta[half][htid] = meta;
        mymeta = meta;
    }

    // ---- speculative loads for in-range targets (pre-barrier) ----
    float vx = 0, vy = 0, vw = 0, vh = 0, vc = 0, cfa0 = 0, cfa1 = 0, cfa2 = 0;
    int   mypos = 0, mya = 0;
    if (inr) {
        mypos = mymeta & 0x3FFF;
        mya   = (mymeta >> 14) & 3;
        const float* ch = base + (size_t)(mya * 25) * HW + mypos;
        vx = ch[0]; vy = ch[HW]; vw = ch[2 * HW]; vh = ch[3 * HW]; vc = ch[4 * HW];
        cfa0 = base[(size_t)( 4) * HW + mypos];
        cfa1 = base[(size_t)(29) * HW + mypos];
        cfa2 = base[(size_t)(54) * HW + mypos];
    }

    // ---- dense math: two 6-wide log-of-products (12 EX2 + 2 LG2) ----
    float a_no = 0.0f;
    if (live) {
        float e0 = __expf(c0.x), e1  = __expf(c0.y), e2  = __expf(c0.z), e3  = __expf(c0.w);
        float e4 = __expf(c1.x), e5  = __expf(c1.y), e6  = __expf(c1.z), e7  = __expf(c1.w);
        float e8 = __expf(c2.x), e9  = __expf(c2.y), e10 = __expf(c2.z), e11 = __expf(c2.w);
        float P1 = (1.0f + e0);
        P1 = fmaf(P1, e1, P1);          // P *= (1+e_k)
        P1 = fmaf(P1, e2, P1);
        P1 = fmaf(P1, e3, P1);
        P1 = fmaf(P1, e4, P1);
        P1 = fmaf(P1, e5, P1);
        float P2 = (1.0f + e6);
        P2 = fmaf(P2, e7,  P2);
        P2 = fmaf(P2, e8,  P2);
        P2 = fmaf(P2, e9,  P2);
        P2 = fmaf(P2, e10, P2);
        P2 = fmaf(P2, e11, P2);
        a_no = __logf(P1) + __logf(P2); // == sum of 12 softplus values
    }
    #pragma unroll
    for (int off = 16; off > 0; off >>= 1)
        a_no += __shfl_down_sync(0xFFFFFFFFu, a_no, off);
    if (lane == 0) s_no[wrp] = a_no;    // plain store, own slot

    __syncthreads();                    // s_acc zeroed, s_meta + s_no published

    // ---- target resolution: dedup survivors, class union, unique ignore bits ----
    if (inr) {
        int      mynz  = (mymeta >> 16) & 7;
        unsigned cm    = 1u << ((mymeta >> 19) & 31);
        bool     alive = true;
        int      subnz = mynz;
        for (int u = 0; u < NT; u++) {
            if (u == htid) continue;
            int mu = s_meta[half][u];
            if ((mu & 0x3FFF) != mypos) continue;
            if (((mu >> 14) & 3) == mya) {
                if (u > htid) alive = false;                 // last duplicate wins
                else          cm |= 1u << ((mu >> 19) & 31); // union earlier classes
            }
            if (u < htid) subnz &= ~((mu >> 16) & 7);        // earlier owner subtracts
        }
        float sub = 0.0f;               // remove ignored cells from dense sum
        if (subnz & 1) sub += spl(cfa0);
        if (subnz & 2) sub += spl(cfa1);
        if (subnz & 4) sub += spl(cfa2);
        if (sub != 0.0f) atomicAdd(&s_acc[5], -sub);

        if (alive) {
            const float* ch = base + (size_t)(mya * 25) * HW + mypos;
            float pc[NCLS];
            #pragma unroll
            for (int c = 0; c < NCLS; c++) pc[c] = ch[(size_t)(5 + c) * HW];
            float scl = 0.0f;
            #pragma unroll
            for (int c = 0; c < NCLS; c++)
                scl += spl(((cm >> c) & 1) ? -pc[c] : pc[c]);
            // BCE(sigm(z), t) = t*spl(-z) + (1-t)*spl(z)
            atomicAdd(&s_acc[0], mytx * spl(-vx) + (1.0f - mytx) * spl(vx));
            atomicAdd(&s_acc[1], myty * spl(-vy) + (1.0f - myty) * spl(vy));
            float dw = vw - mytw, dh = vh - myth;
            atomicAdd(&s_acc[2], dw * dw);
            atomicAdd(&s_acc[3], dh * dh);
            atomicAdd(&s_acc[4], spl(-vc));
            atomicAdd(&s_acc[6], scl);
            atomicAdd(&s_acc[7], 1.0f);
        }
    }
    __syncthreads();                    // s_acc final; LAST block-wide barrier

    // ---- tail: warp 0 only (other warps exit) ----
    if (wrp == 0) {
        float v = 0.0f;
        if (lane < 8) {
            v = s_acc[lane];
            if (lane == 5) {
                #pragma unroll
                for (int w16 = 0; w16 < 16; w16++) v += s_no[w16];
            }
            if (v != 0.0f) atomicAdd(&g_acc[lane], (double)v);
        }
        __threadfence();
        __syncwarp();

        int last = 0;
        if (lane == 0) last = (atomicAdd(&g_ctr, 1) == NBLK - 1);
        last = __shfl_sync(0xFFFFFFFFu, last, 0);

        if (last) {
            __threadfence();
            double A = 0.0;
            if (lane < 8) {
                A = atomicAdd(&g_acc[lane], 0.0);    // parallel coherent reads (MLP=8)
                g_acc[lane] = 0.0;                   // reset for next replay
            }
            double A0 = __shfl_sync(0xFFFFFFFFu, A, 0);
            double A1 = __shfl_sync(0xFFFFFFFFu, A, 1);
            double A2 = __shfl_sync(0xFFFFFFFFu, A, 2);
            double A3 = __shfl_sync(0xFFFFFFFFu, A, 3);
            double A4 = __shfl_sync(0xFFFFFFFFu, A, 4);
            double A5 = __shfl_sync(0xFFFFFFFFu, A, 5);
            double A6 = __shfl_sync(0xFFFFFFFFu, A, 6);
            double A7 = __shfl_sync(0xFFFFFFFFu, A, 7);
            if (lane == 0) {
                out[0] = (float)(2.5 * A0 / NCELL);
                out[1] = (float)(2.5 * A1 / NCELL);
                out[2] = (float)(2.5 * A2 / NCELL);
                out[3] = (float)(2.5 * A3 / NCELL);
                out[4] = (float)((A4 + 0.5 * A5) / NCELL);
                out[5] = (float)(A6 / fmax(A7 * 20.0, 1.0));
                __threadfence();
                g_ctr = 0;
            }
        }
    }
}

extern "C" void kernel_launch(void* const* d_in, const int* in_sizes, int n_in,
                              void* d_out, int out_size) {
    const float* in = (const float*)d_in[0];   // (32,75,104,104)
    const float* tg = (const float*)d_in[1];   // (32,50,5)
    float* out = (float*)d_out;                // 6 floats

    dim3 grid(NBX, BSZ / 2);                   // (11, 16) = 176 blocks x 512 thr
    yolo_fused<<<grid, 512>>>(in, tg, out);
}